// round 17
// baseline (speedup 1.0000x reference)
#include <cuda_runtime.h>
#include <cuda_bf16.h>
#include <cstddef>
#include <cstdint>

#define BN_EPS 1e-5f
#define LOG2E 1.44269504088896340736f

// ---------------------------------------------------------------------------
// Scratch (device globals — no allocation allowed)
// ---------------------------------------------------------------------------
__device__ unsigned short g_qh[4 * 4096 * 64];   // q  [b][n][c] h/l (log2e-scaled)
__device__ unsigned short g_ql[4 * 4096 * 64];
__device__ unsigned short g_kh[4 * 4096 * 64];   // k  [b][n][c]
__device__ unsigned short g_kl[4 * 4096 * 64];
__device__ unsigned short g_vh[4 * 64 * 4096];   // v  [b][c][n]
__device__ unsigned short g_vl[4 * 64 * 4096];
__device__ unsigned short g_x1h[4 * 4096 * 256]; // feature1 transposed [b][n][c]
__device__ unsigned short g_x1l[4 * 4096 * 256];
__device__ unsigned short g_x2h[4 * 4096 * 256]; // feature2 transposed [b][n][c]
__device__ unsigned short g_x2l[4 * 4096 * 256];
__device__ unsigned short g_fh[4 * 4096 * 64];   // attn out [b][n][c]
__device__ unsigned short g_fl[4 * 4096 * 64];
__device__ unsigned short g_wh[884736];          // prepped weights (h)
__device__ unsigned short g_wl[884736];          // prepped weights (l)
__device__ float g_bn[2048];                     // [conv][oc][2] inv,bias
// split-K attention partials: [khalf][b][tile][row][c] and (m,l)
__device__ float g_pO[2][4][32][128][64];
__device__ float g_pm[2][4][32][128];
__device__ float g_pl[2][4][32][128];

// ---------------------------------------------------------------------------
// PTX helpers (baseline sm_80+ features only — harness compiles via compute_103)
// ---------------------------------------------------------------------------
__device__ __forceinline__ uint32_t smem_u32(const void* p) {
    uint32_t a;
    asm("{ .reg .u64 t; cvta.to.shared.u64 t, %1; cvt.u32.u64 %0, t; }"
        : "=r"(a) : "l"(p));
    return a;
}
__device__ __forceinline__ void ldm_x4(uint32_t* r, uint32_t a) {
    asm volatile("ldmatrix.sync.aligned.m8n8.x4.shared.b16 {%0,%1,%2,%3}, [%4];"
                 : "=r"(r[0]), "=r"(r[1]), "=r"(r[2]), "=r"(r[3]) : "r"(a));
}
__device__ __forceinline__ void mma16816(float* d, const uint32_t* a, const uint32_t* b) {
    asm volatile("mma.sync.aligned.m16n8k16.row.col.f32.bf16.bf16.f32 "
                 "{%0,%1,%2,%3}, {%4,%5,%6,%7}, {%8,%9}, {%0,%1,%2,%3};"
                 : "+f"(d[0]), "+f"(d[1]), "+f"(d[2]), "+f"(d[3])
                 : "r"(a[0]), "r"(a[1]), "r"(a[2]), "r"(a[3]),
                   "r"(b[0]), "r"(b[1]));
}
__device__ __forceinline__ uint32_t pack_bf16x2(float lo, float hi) {
    uint32_t r;
    asm("cvt.rn.bf16x2.f32 %0, %1, %2;" : "=r"(r) : "f"(hi), "f"(lo));
    return r;
}
__device__ __forceinline__ void split_bf16(float y, unsigned short& h, unsigned short& l) {
    __nv_bfloat16 hb = __float2bfloat16(y);
    float r = y - __bfloat162float(hb);
    __nv_bfloat16 lb = __float2bfloat16(r);
    h = __bfloat16_as_ushort(hb);
    l = __bfloat16_as_ushort(lb);
}
// cp.async 16B (sm_80 baseline)
__device__ __forceinline__ void cp16(uint32_t dst, const void* src) {
    asm volatile("cp.async.cg.shared.global [%0], [%1], 16;"
                 :: "r"(dst), "l"(src) : "memory");
}
#define CP_COMMIT() asm volatile("cp.async.commit_group;" ::: "memory")
#define CP_WAIT0()  asm volatile("cp.async.wait_group 0;" ::: "memory")

// ---------------------------------------------------------------------------
// Prep kernels
// ---------------------------------------------------------------------------
__global__ void prep_x(const float* __restrict__ f1, const float* __restrict__ f2)
{
    __shared__ float t1[32][33], t2[32][33];
    const int b = blockIdx.z, c0 = blockIdx.y << 5, n0 = blockIdx.x << 5;
    const int tid = threadIdx.x;
    const int a = tid >> 5, e = tid & 31;
#pragma unroll
    for (int i = 0; i < 4; i++) {
        int cl = a + (i << 3);
        size_t src = (((size_t)(b * 256 + c0 + cl)) << 12) + n0 + e;
        t1[cl][e] = f1[src];
        t2[cl][e] = f2[src];
    }
    __syncthreads();
#pragma unroll
    for (int i = 0; i < 4; i++) {
        int nl = a + (i << 3);
        size_t dst = ((size_t)((b << 12) + n0 + nl)) * 256 + c0 + e;
        unsigned short h, l;
        split_bf16(t1[e][nl], h, l);
        g_x1h[dst] = h; g_x1l[dst] = l;
        split_bf16(t2[e][nl], h, l);
        g_x2h[dst] = h; g_x2l[dst] = l;
    }
}

// Merged weight-tiling + BN-folding prep (one launch).
__global__ void prep_wb(
    const float* __restrict__ qw, const float* __restrict__ kw,
    const float* __restrict__ vw, const float* __restrict__ rw,
    const float* qb, const float* qg, const float* qbe, const float* qm, const float* qvv,
    const float* kb, const float* kg, const float* kbe, const float* km, const float* kvv,
    const float* vb, const float* vg, const float* vbe, const float* vm, const float* vvv,
    const float* rb, const float* rg, const float* rbe, const float* rm, const float* rvv)
{
    {
        int t = blockIdx.x * 256 + threadIdx.x;
        if (t < 448) {
            const float *cb, *cg, *cbe, *cm, *cvr;
            int conv, oc;
            if (t < 64)       { conv = 0; oc = t;       cb = qb; cg = qg; cbe = qbe; cm = qm; cvr = qvv; }
            else if (t < 128) { conv = 1; oc = t - 64;  cb = kb; cg = kg; cbe = kbe; cm = km; cvr = kvv; }
            else if (t < 192) { conv = 2; oc = t - 128; cb = vb; cg = vg; cbe = vbe; cm = vm; cvr = vvv; }
            else              { conv = 3; oc = t - 192; cb = rb; cg = rg; cbe = rbe; cm = rm; cvr = rvv; }
            float inv = cg[oc] * rsqrtf(cvr[oc] + BN_EPS);
            g_bn[conv * 512 + oc * 2] = inv;
            g_bn[conv * 512 + oc * 2 + 1] = fmaf(cb[oc], inv, cbe[oc] - cm[oc] * inv);
        }
    }
    for (int i = blockIdx.x * 256 + threadIdx.x; i < 589824; i += gridDim.x * 256) {
        int conv = i / 147456;
        int j = i - conv * 147456;
        const float* w; int CIN;
        if (conv == 0)      { w = qw; CIN = 256; }
        else if (conv == 1) { w = kw; CIN = 256; }
        else if (conv == 2) { w = vw; CIN = 256; }
        else                { w = rw; CIN = 64; }
        int nch = CIN >> 4;
        int icl = j & 15;
        int oc = (j >> 4) & 63;
        int off = (j >> 10) % 9;
        int t2 = j / 9216;
        int chunk = t2 % nch;
        int ocg = t2 / nch;
        float v = w[(((size_t)(ocg * 64 + oc)) * CIN + (chunk << 4) + icl) * 9 + off];
        unsigned short h, l;
        split_bf16(v, h, l);
        int dst = conv * 221184 + (ocg * nch + chunk) * 13824 + ((off << 6) + oc) * 24 + icl;
        g_wh[dst] = h; g_wl[dst] = l;
    }
}

// ---------------------------------------------------------------------------
// Conv mainloop: implicit GEMM, 9 shifted taps, 16-ic chunks, 3-pass bf16.
// Weights pipelined at TAP-ROW granularity (3 taps = one ky row, 2-slot ring):
// cp.async(stage s+1) is issued after the top barrier and overlaps mma(stage s).
// ---------------------------------------------------------------------------
#define XTILE 10560   // 4*66 cells * 40-elem stride
#define WGRP  4608    // 3 taps * 64 oc * 24-elem stride (one stage, shorts)
#define CONV_SMEM ((2 * XTILE + 4 * WGRP) * 2 + 512)   // 79616 B

__device__ __forceinline__ void conv_core(
    const unsigned short* __restrict__ inh,
    const unsigned short* __restrict__ inl,
    int CIN, int wbase, int b, int r0,
    unsigned short* XH, unsigned short* XL,
    unsigned short* WH, unsigned short* WL,   // each 2 slots x WGRP shorts
    float acc[8][4])
{
    const int tid = threadIdx.x;
    const int lane = tid & 31, warp = tid >> 5, l4 = lane & 15;
    const int yy = warp >> 2, xb = (warp & 3) << 4;
    const uint32_t xhb = smem_u32(XH), xlb = smem_u32(XL);
    const uint32_t whb = smem_u32(WH), wlb = smem_u32(WL);

    // zero halo border cells (hx = 0, 65) once — never rewritten
    for (int i = tid; i < 128; i += 256) {
        int hy = i >> 5, r = i & 31;
        int hx = (r >> 4) ? 65 : 0, icl = r & 15;
        int si = (hy * 66 + hx) * 40 + icl;
        XH[si] = 0; XL[si] = 0;
    }

    const int nch = CIN >> 4;
    const int nst = nch * 3;
    const int gy = r0 - 1 + (tid >> 6);
    const int gx = tid & 63;
    const bool inb = (unsigned)gy < 64u;
    const size_t cellbase = inb ? ((size_t)((b << 12) + (gy << 6) + gx)) * CIN : 0;
    const int si0 = ((tid >> 6) * 66 + 1 + gx) * 40;

    // prefetch input cell for chunk 0
    uint4 ih0 = {0,0,0,0}, ih1 = ih0, il0 = ih0, il1 = ih0;
    if (inb) {
        const uint4* ph = (const uint4*)(inh + cellbase);
        const uint4* pl = (const uint4*)(inl + cellbase);
        ih0 = ph[0]; ih1 = ph[1]; il0 = pl[0]; il1 = pl[1];
    }
    // issue weight stage 0 (chunk 0, ky row 0)
    {
        const unsigned short* swh = g_wh + wbase;
        const unsigned short* swl = g_wl + wbase;
        for (int i = tid; i < 576; i += 256) {
            cp16(whb + i * 16, swh + i * 8);
            cp16(wlb + i * 16, swl + i * 8);
        }
        CP_COMMIT();
    }

    for (int s = 0; s < nst; s++) {
        const int g = s % 3;          // ky row of this stage
        CP_WAIT0();                   // stage s landed (thread-local)
        __syncthreads();              // visible to all; all warps done stage s-1

        // issue stage s+1 into the other slot (its previous user was s-1, done)
        if (s + 1 < nst) {
            int sn = s + 1, cn = sn / 3, gn = sn - cn * 3;
            const unsigned short* swh = g_wh + wbase + cn * 13824 + gn * WGRP;
            const unsigned short* swl = g_wl + wbase + cn * 13824 + gn * WGRP;
            uint32_t dh = whb + (uint32_t)(sn & 1) * (WGRP * 2);
            uint32_t dl = wlb + (uint32_t)(sn & 1) * (WGRP * 2);
            for (int i = tid; i < 576; i += 256) {
                cp16(dh + i * 16, swh + i * 8);
                cp16(dl + i * 16, swl + i * 8);
            }
            CP_COMMIT();
        }

        if (g == 0) {
            // store this chunk's input cell (prev chunk fully consumed)
            *(uint4*)(XH + si0) = ih0; *(uint4*)(XH + si0 + 8) = ih1;
            *(uint4*)(XL + si0) = il0; *(uint4*)(XL + si0 + 8) = il1;
            __syncthreads();
        } else if (g == 1 && s + 2 < nst) {
            // prefetch next chunk's input cell during this stage's mma window
            int cn = s / 3 + 1;
            if (inb) {
                const uint4* ph = (const uint4*)(inh + cellbase + (cn << 4));
                const uint4* pl = (const uint4*)(inl + cellbase + (cn << 4));
                ih0 = ph[0]; ih1 = ph[1]; il0 = pl[0]; il1 = pl[1];
            }
        }

        const uint32_t wsh = whb + (uint32_t)(s & 1) * (WGRP * 2);
        const uint32_t wsl = wlb + (uint32_t)(s & 1) * (WGRP * 2);
        const int ky = g;
#pragma unroll
        for (int kx = 0; kx < 3; kx++) {
            uint32_t aro = (uint32_t)((yy + ky) * 66 + xb + l4 + kx) * 80 +
                           ((lane >> 4) << 4);
            uint32_t afh[4], afl[4];
            ldm_x4(afh, xhb + aro);
            ldm_x4(afl, xlb + aro);
            uint32_t bro = (uint32_t)(kx * 64 + l4) * 48 + ((lane >> 4) << 4);
#pragma unroll
            for (int gq = 0; gq < 4; gq++) {
                uint32_t bh[4], bl[4];
                ldm_x4(bh, wsh + bro + gq * 768);
                ldm_x4(bl, wsl + bro + gq * 768);
                uint32_t b0h[2] = {bh[0], bh[2]}, b1h[2] = {bh[1], bh[3]};
                uint32_t b0l[2] = {bl[0], bl[2]}, b1l[2] = {bl[1], bl[3]};
                mma16816(acc[2 * gq],     afh, b0h);
                mma16816(acc[2 * gq],     afl, b0h);
                mma16816(acc[2 * gq],     afh, b0l);
                mma16816(acc[2 * gq + 1], afh, b1h);
                mma16816(acc[2 * gq + 1], afl, b1h);
                mma16816(acc[2 * gq + 1], afh, b1l);
            }
        }
    }
}

// q/k/v fused: blockIdx.y = conv index (0=q from f2, 1=k from f1, 2=v from f1)
__global__ void __launch_bounds__(256, 2) conv_qkv_mma()
{
    extern __shared__ unsigned short smu[];
    unsigned short* XH = smu;
    unsigned short* XL = XH + XTILE;
    unsigned short* WH = XL + XTILE;          // 2 slots x WGRP
    unsigned short* WL = WH + 2 * WGRP;
    float* BN = (float*)(WL + 2 * WGRP);

    const int cidx = blockIdx.y;
    const int b = blockIdx.z;
    const int r0 = blockIdx.x << 1;
    const int n0 = blockIdx.x << 7;
    const int tid = threadIdx.x;

    if (tid < 64) {
        BN[tid * 2]     = g_bn[cidx * 512 + tid * 2];
        BN[tid * 2 + 1] = g_bn[cidx * 512 + tid * 2 + 1];
    }

    const unsigned short* inh = (cidx == 0) ? g_x2h : g_x1h;
    const unsigned short* inl = (cidx == 0) ? g_x2l : g_x1l;

    float acc[8][4];
#pragma unroll
    for (int nc = 0; nc < 8; nc++)
#pragma unroll
        for (int k = 0; k < 4; k++) acc[nc][k] = 0.f;

    conv_core(inh, inl, 256, cidx * 221184, b, r0, XH, XL, WH, WL, acc);

    const int lane = tid & 31, warp = tid >> 5;
    const int gid = lane >> 2, tg = lane & 3;
    const int p0 = n0 + (warp << 4) + gid, p1 = p0 + 8;

    unsigned short *outh, *outl;
    if (cidx == 0)      { outh = g_qh; outl = g_ql; }
    else if (cidx == 1) { outh = g_kh; outl = g_kl; }
    else                { outh = g_vh; outl = g_vl; }

#pragma unroll
    for (int nc = 0; nc < 8; nc++) {
        int c0 = nc * 8 + tg * 2;
        float i0 = BN[c0 * 2],     bb0 = BN[c0 * 2 + 1];
        float i1 = BN[c0 * 2 + 2], bb1 = BN[c0 * 2 + 3];
        float y00 = fmaxf(fmaf(acc[nc][0], i0, bb0), 0.f);
        float y01 = fmaxf(fmaf(acc[nc][1], i1, bb1), 0.f);
        float y10 = fmaxf(fmaf(acc[nc][2], i0, bb0), 0.f);
        float y11 = fmaxf(fmaf(acc[nc][3], i1, bb1), 0.f);
        if (cidx == 0) {   // fold log2e into q so attention runs in exp2 domain
            y00 *= LOG2E; y01 *= LOG2E; y10 *= LOG2E; y11 *= LOG2E;
        }
        if (cidx < 2) {
            unsigned short h00, l00, h01, l01, h10, l10, h11, l11;
            split_bf16(y00, h00, l00); split_bf16(y01, h01, l01);
            split_bf16(y10, h10, l10); split_bf16(y11, h11, l11);
            size_t a0 = ((size_t)((b << 12) + p0)) * 64 + c0;
            size_t a1 = ((size_t)((b << 12) + p1)) * 64 + c0;
            *(uint32_t*)(outh + a0) = ((uint32_t)h01 << 16) | h00;
            *(uint32_t*)(outl + a0) = ((uint32_t)l01 << 16) | l00;
            *(uint32_t*)(outh + a1) = ((uint32_t)h11 << 16) | h10;
            *(uint32_t*)(outl + a1) = ((uint32_t)l11 << 16) | l10;
        } else {
            unsigned short h, l;
            size_t ga = ((size_t)(b * 64 + c0)) << 12, gb = ga + 4096;
            split_bf16(y00, h, l); outh[ga + p0] = h; outl[ga + p0] = l;
            split_bf16(y01, h, l); outh[gb + p0] = h; outl[gb + p0] = l;
            split_bf16(y10, h, l); outh[ga + p1] = h; outl[ga + p1] = l;
            split_bf16(y11, h, l); outh[gb + p1] = h; outl[gb + p1] = l;
        }
    }
}

// final conv: blockIdx.y = oc-group (0..3), input g_fh/g_fl [b][n][64]
__global__ void __launch_bounds__(256, 2) conv_final_mma(const float* __restrict__ resid,
                                                         float* __restrict__ out)
{
    extern __shared__ unsigned short smu[];
    unsigned short* XH = smu;
    unsigned short* XL = XH + XTILE;
    unsigned short* WH = XL + XTILE;
    unsigned short* WL = WH + 2 * WGRP;
    float* BN = (float*)(WL + 2 * WGRP);

    const int ocg = blockIdx.y;
    const int b = blockIdx.z;
    const int r0 = blockIdx.x << 1;
    const int n0 = blockIdx.x << 7;
    const int tid = threadIdx.x;

    if (tid < 64) {
        BN[tid * 2]     = g_bn[3 * 512 + ocg * 128 + tid * 2];
        BN[tid * 2 + 1] = g_bn[3 * 512 + ocg * 128 + tid * 2 + 1];
    }

    float acc[8][4];
#pragma unroll
    for (int nc = 0; nc < 8; nc++)
#pragma unroll
        for (int k = 0; k < 4; k++) acc[nc][k] = 0.f;

    conv_core(g_fh, g_fl, 64, 3 * 221184 + ocg * 55296, b, r0, XH, XL, WH, WL, acc);

    const int lane = tid & 31, warp = tid >> 5;
    const int gid = lane >> 2, tg = lane & 3;
    const int p0 = n0 + (warp << 4) + gid, p1 = p0 + 8;

#pragma unroll
    for (int nc = 0; nc < 8; nc++) {
        int c0 = nc * 8 + tg * 2;
        float i0 = BN[c0 * 2],     bb0 = BN[c0 * 2 + 1];
        float i1 = BN[c0 * 2 + 2], bb1 = BN[c0 * 2 + 3];
        float y00 = fmaxf(fmaf(acc[nc][0], i0, bb0), 0.f);
        float y01 = fmaxf(fmaf(acc[nc][1], i1, bb1), 0.f);
        float y10 = fmaxf(fmaf(acc[nc][2], i0, bb0), 0.f);
        float y11 = fmaxf(fmaf(acc[nc][3], i1, bb1), 0.f);
        size_t ga = ((size_t)(b * 256 + (ocg << 6) + c0)) << 12;
        size_t gb = ga + 4096;
        out[ga + p0] = y00 + resid[ga + p0];
        out[gb + p0] = y01 + resid[gb + p0];
        out[ga + p1] = y10 + resid[ga + p1];
        out[gb + p1] = y11 + resid[gb + p1];
    }
}

// ---------------------------------------------------------------------------
// Flash attention SPLIT-K partial (log2 domain: q pre-scaled by log2e, so
// softmax uses raw exp2f). grid (32 q-tiles, 2 key-halves, 4 b) = 256 blocks.
// ---------------------------------------------------------------------------
#define QS 72  // smem row stride (bf16 elems), 144 bytes

__global__ void __launch_bounds__(256, 2) attn_partial_kernel()
{
    extern __shared__ unsigned short smu[];
    unsigned short* Qh = smu;            // 128 x QS
    unsigned short* Ql = smu + 9216;
    const uint32_t KHB = smem_u32(smu + 18432);
    const uint32_t KLB = smem_u32(smu + 27648);
    const uint32_t VHB = smem_u32(smu + 36864);
    const uint32_t VLB = smem_u32(smu + 46080);

    const int tid  = threadIdx.x;
    const int lane = tid & 31;
    const int warp = tid >> 5;
    const int gid  = lane >> 2, tg = lane & 3;
    const int tile = blockIdx.x;
    const int kh   = blockIdx.y;
    const int b    = blockIdx.z;
    const int n0 = tile << 7;
    const int k0 = kh << 5;
    const int mbase = warp << 4;

    {
        int r = tid >> 1, h = (tid & 1) << 5;
        size_t src = ((size_t)(b * 4096 + n0 + r)) * 64 + h;
        const uint4* sh = (const uint4*)(g_qh + src);
        const uint4* sl = (const uint4*)(g_ql + src);
        uint4* dh = (uint4*)(Qh + r * QS + h);
        uint4* dl = (uint4*)(Ql + r * QS + h);
#pragma unroll
        for (int i = 0; i < 4; i++) { dh[i] = sh[i]; dl[i] = sl[i]; }
    }

    const int sr = tid >> 2, sc = (tid & 3) << 4;
    const uint32_t sro = (uint32_t)sr * (QS * 2) + sc * 2;
    const size_t kgbase = ((size_t)(b * 4096 + sr)) * 64 + sc;
    const size_t vgbase = (((size_t)(b * 64 + sr)) << 12) + sc;

#define STAGE_KV(t, d) do {                                                   \
        const unsigned short* skh = g_kh + kgbase + ((size_t)(t) << 12);      \
        const unsigned short* skl = g_kl + kgbase + ((size_t)(t) << 12);      \
        const unsigned short* svh = g_vh + vgbase + ((t) << 6);               \
        const unsigned short* svl = g_vl + vgbase + ((t) << 6);               \
        uint32_t o = (d) * 9216 + sro;                                        \
        cp16(KHB + o, skh);      cp16(KHB + o + 16, skh + 8);                 \
        cp16(KLB + o, skl);      cp16(KLB + o + 16, skl + 8);                 \
        cp16(VHB + o, svh);      cp16(VHB + o + 16, svh + 8);                 \
        cp16(VLB + o, svl);      cp16(VLB + o + 16, svl + 8);                 \
    } while (0)

    STAGE_KV(k0, 0);
    CP_COMMIT();
    __syncthreads();

    uint32_t qfh[4][4], qfl[4][4];
    {
        uint32_t qhb = smem_u32(Qh), qlb = smem_u32(Ql);
        uint32_t ro = (uint32_t)(mbase + (lane & 15)) * (QS * 2) + ((lane >> 4) << 4);
#pragma unroll
        for (int i = 0; i < 4; i++) {
            ldm_x4(qfh[i], qhb + ro + i * 32);
            ldm_x4(qfl[i], qlb + ro + i * 32);
        }
    }

    const int l4 = lane & 15;
    const uint32_t b4ro = (uint32_t)l4 * (QS * 2) + ((lane >> 4) << 4);

    float O[8][4];
    float mi0 = -1e30f, mi1 = -1e30f, li0 = 0.f, li1 = 0.f;
#pragma unroll
    for (int j = 0; j < 8; j++)
#pragma unroll
        for (int k = 0; k < 4; k++) O[j][k] = 0.f;

    for (int t = 0; t < 32; t++) {
        CP_WAIT0();
        __syncthreads();

        if (t < 31) {
            STAGE_KV(k0 + t + 1, (t + 1) & 1);
            CP_COMMIT();
        }

        const uint32_t bofs = (t & 1) * 9216;
        const uint32_t khb = KHB + bofs, klb = KLB + bofs;
        const uint32_t vhb = VHB + bofs, vlb = VLB + bofs;

        float sacc[8][4];
#pragma unroll
        for (int j = 0; j < 8; j++)
#pragma unroll
            for (int k = 0; k < 4; k++) sacc[j][k] = 0.f;

#pragma unroll
        for (int jp = 0; jp < 4; jp++) {
#pragma unroll
            for (int i = 0; i < 4; i++) {
                uint32_t off = (uint32_t)(16 * jp) * (QS * 2) + b4ro + i * 32;
                uint32_t bh[4], bl[4];
                ldm_x4(bh, khb + off);
                ldm_x4(bl, klb + off);
                uint32_t b0h[2] = {bh[0], bh[2]}, b1h[2] = {bh[1], bh[3]};
                uint32_t b0l[2] = {bl[0], bl[2]}, b1l[2] = {bl[1], bl[3]};
                mma16816(sacc[2 * jp],     qfh[i], b0h);
                mma16816(sacc[2 * jp],     qfl[i], b0h);
                mma16816(sacc[2 * jp],     qfh[i], b0l);
                mma16816(sacc[2 * jp + 1], qfh[i], b1h);
                mma16816(sacc[2 * jp + 1], qfl[i], b1h);
                mma16816(sacc[2 * jp + 1], qfh[i], b1l);
            }
        }

        float rm0 = -1e30f, rm1 = -1e30f;
#pragma unroll
        for (int j = 0; j < 8; j++) {
            rm0 = fmaxf(rm0, fmaxf(sacc[j][0], sacc[j][1]));
            rm1 = fmaxf(rm1, fmaxf(sacc[j][2], sacc[j][3]));
        }
        rm0 = fmaxf(rm0, __shfl_xor_sync(0xffffffffu, rm0, 1));
        rm0 = fmaxf(rm0, __shfl_xor_sync(0xffffffffu, rm0, 2));
        rm1 = fmaxf(rm1, __shfl_xor_sync(0xffffffffu, rm1, 1));
        rm1 = fmaxf(rm1, __shfl_xor_sync(0xffffffffu, rm1, 2));

        float mn0 = fmaxf(mi0, rm0), mn1 = fmaxf(mi1, rm1);
        float c0 = exp2f(mi0 - mn0), c1 = exp2f(mi1 - mn1);
        mi0 = mn0; mi1 = mn1;

        float rs0 = 0.f, rs1 = 0.f;
        uint32_t ph[16], pl[16];
#pragma unroll
        for (int j = 0; j < 8; j++) {
            float p00 = exp2f(sacc[j][0] - mi0);
            float p01 = exp2f(sacc[j][1] - mi0);
            float p10 = exp2f(sacc[j][2] - mi1);
            float p11 = exp2f(sacc[j][3] - mi1);
            rs0 += p00 + p01;
            rs1 += p10 + p11;
            uint32_t h0 = pack_bf16x2(p00, p01);
            uint32_t h1 = pack_bf16x2(p10, p11);
            ph[2 * j]     = h0;
            ph[2 * j + 1] = h1;
            float r00 = p00 - __uint_as_float(h0 << 16);
            float r01 = p01 - __uint_as_float(h0 & 0xffff0000u);
            float r10 = p10 - __uint_as_float(h1 << 16);
            float r11 = p11 - __uint_as_float(h1 & 0xffff0000u);
            pl[2 * j]     = pack_bf16x2(r00, r01);
            pl[2 * j + 1] = pack_bf16x2(r10, r11);
        }
        rs0 += __shfl_xor_sync(0xffffffffu, rs0, 1);
        rs0 += __shfl_xor_sync(0xffffffffu, rs0, 2);
        rs1 += __shfl_xor_sync(0xffffffffu, rs1, 1);
        rs1 += __shfl_xor_sync(0xffffffffu, rs1, 2);
        li0 = li0 * c0 + rs0;
        li1 = li1 * c1 + rs1;

#pragma unroll
        for (int j = 0; j < 8; j++) {
            O[j][0] *= c0; O[j][1] *= c0;
            O[j][2] *= c1; O[j][3] *= c1;
        }

#pragma unroll
        for (int jp = 0; jp < 4; jp++) {
#pragma unroll
            for (int i = 0; i < 4; i++) {
                uint32_t off = (uint32_t)(16 * jp) * (QS * 2) + b4ro + i * 32;
                uint32_t bh[4], bl[4];
                ldm_x4(bh, vhb + off);
                ldm_x4(bl, vlb + off);
                uint32_t b0h[2] = {bh[0], bh[2]}, b1h[2] = {bh[1], bh[3]};
                uint32_t b0l[2] = {bl[0], bl[2]}, b1l[2] = {bl[1], bl[3]};
                mma16816(O[2 * jp],     &ph[4 * i], b0h);
                mma16816(O[2 * jp],     &pl[4 * i], b0h);
                mma16816(O[2 * jp],     &ph[4 * i], b0l);
                mma16816(O[2 * jp + 1], &ph[4 * i], b1h);
                mma16816(O[2 * jp + 1], &pl[4 * i], b1h);
                mma16816(O[2 * jp + 1], &ph[4 * i], b1l);
            }
        }
    }

    {
        int r0n = mbase + gid, r1n = r0n + 8;
        float* pO0 = &g_pO[kh][b][tile][r0n][0];
        float* pO1 = &g_pO[kh][b][tile][r1n][0];
#pragma unroll
        for (int j = 0; j < 8; j++) {
            int c = 8 * j + 2 * tg;
            pO0[c]     = O[j][0];
            pO0[c + 1] = O[j][1];
            pO1[c]     = O[j][2];
            pO1[c + 1] = O[j][3];
        }
        if (tg == 0) {
            g_pm[kh][b][tile][r0n] = mi0;
            g_pl[kh][b][tile][r0n] = li0;
            g_pm[kh][b][tile][r1n] = mi1;
            g_pl[kh][b][tile][r1n] = li1;
        }
    }
#undef STAGE_KV
}

// Merge the two key-half partials -> split-bf16 f [b][n][c].
// NOTE: g_pm is in log2 units (q pre-scaled) -> exp2f here.
__global__ void attn_merge_kernel()
{
    const int tile = blockIdx.x, b = blockIdx.y;
    const int tid = threadIdx.x;
    const int row = tid >> 1, c0 = (tid & 1) << 5;

    float m0 = g_pm[0][b][tile][row], l0 = g_pl[0][b][tile][row];
    float m1 = g_pm[1][b][tile][row], l1 = g_pl[1][b][tile][row];
    float m = fmaxf(m0, m1);
    float e0 = exp2f(m0 - m), e1 = exp2f(m1 - m);
    float inv = 1.f / (l0 * e0 + l1 * e1);
    float w0 = e0 * inv, w1 = e1 * inv;

    const float4* O0 = (const float4*)&g_pO[0][b][tile][row][c0];
    const float4* O1 = (const float4*)&g_pO[1][b][tile][row][c0];
    size_t dst = ((size_t)((b << 12) + (tile << 7) + row)) * 64 + c0;
#pragma unroll
    for (int i = 0; i < 8; i++) {
        float4 a = O0[i], c = O1[i];
        float y0 = a.x * w0 + c.x * w1;
        float y1 = a.y * w0 + c.y * w1;
        float y2 = a.z * w0 + c.z * w1;
        float y3 = a.w * w0 + c.w * w1;
        unsigned short h0, lo0, h1, lo1, h2, lo2, h3, lo3;
        split_bf16(y0, h0, lo0); split_bf16(y1, h1, lo1);
        split_bf16(y2, h2, lo2); split_bf16(y3, h3, lo3);
        uint2 ph = make_uint2(((uint32_t)h1 << 16) | h0, ((uint32_t)h3 << 16) | h2);
        uint2 pl = make_uint2(((uint32_t)lo1 << 16) | lo0, ((uint32_t)lo3 << 16) | lo2);
        *(uint2*)(g_fh + dst + i * 4) = ph;
        *(uint2*)(g_fl + dst + i * 4) = pl;
    }
}

// ---------------------------------------------------------------------------
extern "C" void kernel_launch(void* const* d_in, const int* in_sizes, int n_in,
                              void* d_out, int out_size)
{
    (void)in_sizes; (void)n_in; (void)out_size;

    const float* f1  = (const float*)d_in[0];
    const float* f2  = (const float*)d_in[1];
    const float* qw  = (const float*)d_in[2];
    const float* qb  = (const float*)d_in[3];
    const float* qg  = (const float*)d_in[4];
    const float* qbe = (const float*)d_in[5];
    const float* qm  = (const float*)d_in[6];
    const float* qv  = (const float*)d_in[7];
    const float* kw  = (const float*)d_in[8];
    const float* kb  = (const float*)d_in[9];
    const float* kg  = (const float*)d_in[10];
    const float* kbe = (const float*)d_in[11];
    const float* km  = (const float*)d_in[12];
    const float* kv  = (const float*)d_in[13];
    const float* vw  = (const float*)d_in[14];
    const float* vb  = (const float*)d_in[15];
    const float* vg  = (const float*)d_in[16];
    const float* vbe = (const float*)d_in[17];
    const float* vm  = (const float*)d_in[18];
    const float* vv  = (const float*)d_in[19];
    const float* rw  = (const float*)d_in[20];
    const float* rb  = (const float*)d_in[21];
    const float* rg  = (const float*)d_in[22];
    const float* rbe = (const float*)d_in[23];
    const float* rm  = (const float*)d_in[24];
    const float* rv  = (const float*)d_in[25];
    float* out = (float*)d_out;

    prep_x<<<dim3(128, 8, 4), 256>>>(f1, f2);
    prep_wb<<<576, 256>>>(qw, kw, vw, rw,
                          qb, qg, qbe, qm, qv,
                          kb, kg, kbe, km, kv,
                          vb, vg, vbe, vm, vv,
                          rb, rg, rbe, rm, rv);

    cudaFuncSetAttribute(conv_qkv_mma,
                         cudaFuncAttributeMaxDynamicSharedMemorySize, CONV_SMEM);
    cudaFuncSetAttribute(conv_final_mma,
                         cudaFuncAttributeMaxDynamicSharedMemorySize, CONV_SMEM);

    conv_qkv_mma<<<dim3(32, 3, 4), 256, CONV_SMEM>>>();

    const int attn_smem = 55296 * (int)sizeof(unsigned short);  // 110592 B
    cudaFuncSetAttribute(attn_partial_kernel,
                         cudaFuncAttributeMaxDynamicSharedMemorySize, attn_smem);
    attn_partial_kernel<<<dim3(32, 2, 4), 256, attn_smem>>>();
    attn_merge_kernel<<<dim3(32, 4), 256>>>();

    conv_final_mma<<<dim3(32, 4, 4), 256, CONV_SMEM>>>(f1, out);
}